// round 9
// baseline (speedup 1.0000x reference)
#include <cuda_runtime.h>
#include <cuda_bf16.h>

// Problem dims
#define NN 8192      // nodes
#define EE 16384     // edges
#define GG 512       // graphs
#define IND 235      // input dim
#define HD 64        // hidden
#define EDIM 52      // edge feature dim
#define KP 240       // padded K (235 -> 240, multiple of 8)
#define JB 3456      // U columns: 3328 (d*64+h) + 64 (c0) + 64 (root)
#define MROWS 15040  // IN*H

typedef unsigned long long ull;

// ---------------- scratch (device globals; no allocation allowed) ----------
__device__ float g_Xp[NN * KP];       // 7.9 MB  padded x
__device__ float g_Bp[KP * JB];       // 3.3 MB  combined B matrix (rows padded w/ zeros)
__device__ float g_U[NN * JB];        // 113 MB  U = Xp @ Bp
__device__ float g_agg[NN * HD];      // 2.1 MB
__device__ float g_pool[GG * HD];
__device__ int   g_cnt[GG];

// ---------------- f32x2 helpers -------------------------------------------
__device__ __forceinline__ ull ffma2(ull a, ull b, ull c) {
    ull d;
    asm("fma.rn.f32x2 %0, %1, %2, %3;" : "=l"(d) : "l"(a), "l"(b), "l"(c));
    return d;
}
__device__ __forceinline__ ull pack2(float lo, float hi) {
    ull r;
    asm("mov.b64 %0, {%1, %2};" : "=l"(r) : "f"(lo), "f"(hi));
    return r;
}
__device__ __forceinline__ float2 unpack2(ull v) {
    float2 r;
    asm("mov.b64 {%0, %1}, %2;" : "=f"(r.x), "=f"(r.y) : "l"(v));
    return r;
}

// ---------------- prep: pad x, zero scratch, copy root cols ----------------
__global__ void prep_kernel(const float* __restrict__ x,
                            const float* __restrict__ root) {
    const int NPAD = NN * KP;
    const int NZ1  = NN * HD;
    const int NZ2  = GG * HD;
    const int NZ3  = GG;
    const int NR   = IND * HD;
    const int NBP  = (KP - IND) * JB;
    const int total = NPAD + NZ1 + NZ2 + NZ3 + NR + NBP;
    for (int idx = blockIdx.x * blockDim.x + threadIdx.x; idx < total;
         idx += gridDim.x * blockDim.x) {
        int t = idx;
        if (t < NPAD) {
            int n = t / KP, i = t - n * KP;
            g_Xp[t] = (i < IND) ? x[n * IND + i] : 0.0f;
            continue;
        }
        t -= NPAD;
        if (t < NZ1) { g_agg[t] = 0.0f; continue; }
        t -= NZ1;
        if (t < NZ2) { g_pool[t] = 0.0f; continue; }
        t -= NZ2;
        if (t < NZ3) { g_cnt[t] = 0; continue; }
        t -= NZ3;
        if (t < NR) {
            int i = t >> 6, h = t & 63;
            g_Bp[i * JB + 3392 + h] = root[t];   // root[i,h]
            continue;
        }
        t -= NR;
        g_Bp[IND * JB + t] = 0.0f;               // zero padded K-rows
    }
}

// ---------------- build C = W2 @ W1 and c0 into Bp -------------------------
// warp per output row m in [0, 15040); lane handles d = lane, lane+32
__global__ void buildC_kernel(const float* __restrict__ W1,
                              const float* __restrict__ b1,
                              const float* __restrict__ W2,
                              const float* __restrict__ b2) {
    int m = (blockIdx.x * blockDim.x + threadIdx.x) >> 5;
    int lane = threadIdx.x & 31;
    if (m >= MROWS) return;
    const float* w2row = W2 + m * 128;
    int d0 = lane, d1 = lane + 32;
    float acc0 = 0.f, acc1 = 0.f, accb = 0.f;
#pragma unroll 4
    for (int k = 0; k < 128; ++k) {
        float w2 = __ldg(w2row + k);             // broadcast across warp
        float w1a = __ldg(W1 + k * EDIM + d0);
        float w1b = (d1 < EDIM) ? __ldg(W1 + k * EDIM + d1) : 0.0f;
        acc0 = fmaf(w2, w1a, acc0);
        acc1 = fmaf(w2, w1b, acc1);
        accb = fmaf(w2, __ldg(b1 + k), accb);
    }
    int i = m >> 6, h = m & 63;
    float* brow = g_Bp + i * JB;
    brow[d0 * 64 + h] = acc0;
    if (d1 < EDIM) brow[d1 * 64 + h] = acc1;
    if (lane == 0) brow[3328 + h] = accb + b2[m];
}

// ---------------- main GEMM: U[8192,3456] = Xp[8192,240] @ Bp[240,3456] ----
// 128x128 tile, BK=8, 256 threads, 8x8 per thread via packed f32x2 FFMA
#define BM 128
#define BN 128
#define BK 8
__global__ void __launch_bounds__(256)
gemm_kernel() {
    __shared__ float As[BK][BM];
    __shared__ float Bs[BK][BN];

    const int tid = threadIdx.x;
    const int m0 = blockIdx.y * BM;
    const int n0 = blockIdx.x * BN;

    // A load: thread -> (row = tid/2, 4 consecutive k at (tid&1)*4)
    const int ra = tid >> 1;
    const int ka = (tid & 1) * 4;
    // B load: thread -> (k = tid/32, 4 consecutive n at (tid&31)*4)
    const int kb = tid >> 5;
    const int nb = (tid & 31) * 4;
    // compute: 16x16 thread grid, 8x8 outputs each
    const int tm0 = (tid >> 4) * 8;
    const int tn0 = (tid & 15) * 8;

    const float* abase = g_Xp + (m0 + ra) * KP + ka;

    ull acc[8][4];
#pragma unroll
    for (int mm = 0; mm < 8; ++mm)
#pragma unroll
        for (int nn = 0; nn < 4; ++nn) acc[mm][nn] = 0ULL;

    // prologue prefetch
    float2 pa0 = *(const float2*)(abase);
    float2 pa1 = *(const float2*)(abase + 2);
    float4 pb  = *(const float4*)(g_Bp + kb * JB + n0 + nb);

    for (int k0 = 0; k0 < KP; k0 += BK) {
        As[ka + 0][ra] = pa0.x;
        As[ka + 1][ra] = pa0.y;
        As[ka + 2][ra] = pa1.x;
        As[ka + 3][ra] = pa1.y;
        *(float4*)&Bs[kb][nb] = pb;
        __syncthreads();

        if (k0 + BK < KP) {
            pa0 = *(const float2*)(abase + k0 + BK);
            pa1 = *(const float2*)(abase + k0 + BK + 2);
            pb  = *(const float4*)(g_Bp + (k0 + BK + kb) * JB + n0 + nb);
        }

#pragma unroll
        for (int k = 0; k < BK; ++k) {
            float4 a0 = *(const float4*)&As[k][tm0];
            float4 a1 = *(const float4*)&As[k][tm0 + 4];
            float4 bv0 = *(const float4*)&Bs[k][tn0];
            float4 bv1 = *(const float4*)&Bs[k][tn0 + 4];
            ull b0 = pack2(bv0.x, bv0.y);
            ull b1 = pack2(bv0.z, bv0.w);
            ull b2 = pack2(bv1.x, bv1.y);
            ull b3 = pack2(bv1.z, bv1.w);
            float am[8] = {a0.x, a0.y, a0.z, a0.w, a1.x, a1.y, a1.z, a1.w};
#pragma unroll
            for (int mm = 0; mm < 8; ++mm) {
                ull ad = pack2(am[mm], am[mm]);
                acc[mm][0] = ffma2(ad, b0, acc[mm][0]);
                acc[mm][1] = ffma2(ad, b1, acc[mm][1]);
                acc[mm][2] = ffma2(ad, b2, acc[mm][2]);
                acc[mm][3] = ffma2(ad, b3, acc[mm][3]);
            }
        }
        __syncthreads();
    }

#pragma unroll
    for (int mm = 0; mm < 8; ++mm) {
        float* urow = g_U + (m0 + tm0 + mm) * JB + n0 + tn0;
        float2 p0 = unpack2(acc[mm][0]);
        float2 p1 = unpack2(acc[mm][1]);
        float2 p2 = unpack2(acc[mm][2]);
        float2 p3 = unpack2(acc[mm][3]);
        float4 v0 = make_float4(p0.x, p0.y, p1.x, p1.y);
        float4 v1 = make_float4(p2.x, p2.y, p3.x, p3.y);
        *(float4*)(urow)     = v0;
        *(float4*)(urow + 4) = v1;
    }
}

// ---------------- edge kernel: gather U[src], contract ea, scatter to agg --
// warp per edge; lane handles h = 2*lane, 2*lane+1
__global__ void edge_kernel(const int* __restrict__ ei,
                            const float* __restrict__ ea) {
    int e = (blockIdx.x * blockDim.x + threadIdx.x) >> 5;
    int lane = threadIdx.x & 31;
    if (e >= EE) return;
    int src = ei[e];
    int dst = ei[EE + e];
    const float* urow = g_U + src * JB;
    const float* earow = ea + e * EDIM;

    float2 acc = *(const float2*)(urow + 3328 + 2 * lane);  // c0 contribution
#pragma unroll 4
    for (int d = 0; d < EDIM; ++d) {
        float ed = __ldg(earow + d);
        float2 u = *(const float2*)(urow + d * 64 + 2 * lane);
        acc.x = fmaf(ed, u.x, acc.x);
        acc.y = fmaf(ed, u.y, acc.y);
    }
    atomicAdd(&g_agg[dst * 64 + 2 * lane],     acc.x);
    atomicAdd(&g_agg[dst * 64 + 2 * lane + 1], acc.y);
}

// ---------------- node kernel: relu(agg + x@root + b), pool scatter --------
__global__ void node_kernel(const int* __restrict__ batch,
                            const float* __restrict__ conv_b) {
    int n = (blockIdx.x * blockDim.x + threadIdx.x) >> 5;
    int lane = threadIdx.x & 31;
    if (n >= NN) return;
    float2 a  = *(const float2*)&g_agg[n * 64 + 2 * lane];
    float2 xr = *(const float2*)(g_U + n * JB + 3392 + 2 * lane);
    float ox = fmaxf(a.x + xr.x + __ldg(conv_b + 2 * lane),     0.0f);
    float oy = fmaxf(a.y + xr.y + __ldg(conv_b + 2 * lane + 1), 0.0f);
    int g = batch[n];
    atomicAdd(&g_pool[g * 64 + 2 * lane],     ox);
    atomicAdd(&g_pool[g * 64 + 2 * lane + 1], oy);
    if (lane == 0) atomicAdd(&g_cnt[g], 1);
}

// ---------------- fused MLP head: block per graph --------------------------
__global__ void mlp_kernel(const float* __restrict__ fw1, const float* __restrict__ fb1,
                           const float* __restrict__ fw2, const float* __restrict__ fb2,
                           const float* __restrict__ fw3, const float* __restrict__ fb3,
                           const float* __restrict__ fw4, const float* __restrict__ fb4,
                           float* __restrict__ out) {
    int g = blockIdx.x;
    int t = threadIdx.x;
    __shared__ float s0[64], s1[128], s2[256], s3[128];

    if (t < 64) {
        float c = fmaxf((float)g_cnt[g], 1.0f);
        s0[t] = g_pool[g * 64 + t] / c;
    }
    __syncthreads();

    if (t < 128) {
        float a = fb1[t];
#pragma unroll 8
        for (int j = 0; j < 64; ++j) a = fmaf(__ldg(fw1 + t * 64 + j), s0[j], a);
        s1[t] = fmaxf(a, 0.0f);
    }
    __syncthreads();

    {
        float a = fb2[t];
#pragma unroll 8
        for (int j = 0; j < 128; ++j) a = fmaf(__ldg(fw2 + t * 128 + j), s1[j], a);
        s2[t] = fmaxf(a, 0.0f);
    }
    __syncthreads();

    if (t < 128) {
        float a = fb3[t];
#pragma unroll 8
        for (int j = 0; j < 256; ++j) a = fmaf(__ldg(fw3 + t * 256 + j), s2[j], a);
        s3[t] = fmaxf(a, 0.0f);
    }
    __syncthreads();

    if (t < 32) {
        float a = 0.0f;
        for (int j = t; j < 128; j += 32) a = fmaf(__ldg(fw4 + j), s3[j], a);
#pragma unroll
        for (int o = 16; o; o >>= 1) a += __shfl_down_sync(0xffffffffu, a, o);
        if (t == 0) out[g] = a + fb4[0];
    }
}

// ---------------- launcher -------------------------------------------------
extern "C" void kernel_launch(void* const* d_in, const int* in_sizes, int n_in,
                              void* d_out, int out_size) {
    const float* x      = (const float*)d_in[0];
    const int*   ei     = (const int*)  d_in[1];
    const float* ea     = (const float*)d_in[2];
    const int*   batch  = (const int*)  d_in[3];
    const float* W1     = (const float*)d_in[4];
    const float* b1     = (const float*)d_in[5];
    const float* W2     = (const float*)d_in[6];
    const float* b2     = (const float*)d_in[7];
    const float* root   = (const float*)d_in[8];
    const float* conv_b = (const float*)d_in[9];
    const float* fw1    = (const float*)d_in[10];
    const float* fb1    = (const float*)d_in[11];
    const float* fw2    = (const float*)d_in[12];
    const float* fb2    = (const float*)d_in[13];
    const float* fw3    = (const float*)d_in[14];
    const float* fb3    = (const float*)d_in[15];
    const float* fw4    = (const float*)d_in[16];
    const float* fb4    = (const float*)d_in[17];
    float* out = (float*)d_out;

    prep_kernel<<<4096, 256>>>(x, root);
    buildC_kernel<<<(MROWS + 7) / 8, 256>>>(W1, b1, W2, b2);
    gemm_kernel<<<dim3(JB / BN, NN / BM), 256>>>();
    edge_kernel<<<EE / 8, 256>>>(ei, ea);
    node_kernel<<<NN / 8, 256>>>(batch, conv_b);
    mlp_kernel<<<GG, 256>>>(fw1, fb1, fw2, fb2, fw3, fb3, fw4, fb4, out);
}

// round 10
// speedup vs baseline: 1.5240x; 1.5240x over previous
#include <cuda_runtime.h>
#include <cuda_bf16.h>

// Problem dims
#define NN 8192      // nodes
#define EE 16384     // edges
#define GG 512       // graphs
#define IND 235      // input dim
#define HD 64        // hidden
#define EDIM 52      // edge feature dim
#define KP 240       // padded K (235 -> 240, multiple of 16)
#define JB 3456      // U columns: 3328 (d*64+h) + 64 (c0) + 64 (root)
#define MROWS 15040  // IN*H

// ---------------- scratch (device globals; no allocation allowed) ----------
__device__ float g_Xp[NN * KP];       // 7.9 MB  padded x
__device__ float g_Bp[KP * JB];       // 3.3 MB  combined B matrix (rows padded w/ zeros)
__device__ float g_U[NN * JB];        // 113 MB  U = Xp @ Bp
__device__ float g_agg[NN * HD];      // 2.1 MB
__device__ float g_pool[GG * HD];
__device__ int   g_cnt[GG];

// ---------------- tf32 helpers --------------------------------------------
__device__ __forceinline__ float to_tf32(float x) {
    unsigned u;
    asm("cvt.rna.tf32.f32 %0, %1;" : "=r"(u) : "f"(x));
    return __uint_as_float(u);
}
__device__ __forceinline__ void mma_tf32(float* c,
                                         unsigned a0, unsigned a1, unsigned a2, unsigned a3,
                                         unsigned b0, unsigned b1) {
    asm volatile(
        "mma.sync.aligned.m16n8k8.row.col.f32.tf32.tf32.f32 "
        "{%0,%1,%2,%3}, {%4,%5,%6,%7}, {%8,%9}, {%0,%1,%2,%3};"
        : "+f"(c[0]), "+f"(c[1]), "+f"(c[2]), "+f"(c[3])
        : "r"(a0), "r"(a1), "r"(a2), "r"(a3), "r"(b0), "r"(b1));
}

// ---------------- prep: pad x, zero scratch, copy root cols ----------------
__global__ void prep_kernel(const float* __restrict__ x,
                            const float* __restrict__ root) {
    const int NPAD = NN * KP;
    const int NZ1  = NN * HD;
    const int NZ2  = GG * HD;
    const int NZ3  = GG;
    const int NR   = IND * HD;
    const int NBP  = (KP - IND) * JB;
    const int total = NPAD + NZ1 + NZ2 + NZ3 + NR + NBP;
    for (int idx = blockIdx.x * blockDim.x + threadIdx.x; idx < total;
         idx += gridDim.x * blockDim.x) {
        int t = idx;
        if (t < NPAD) {
            int n = t / KP, i = t - n * KP;
            g_Xp[t] = (i < IND) ? x[n * IND + i] : 0.0f;
            continue;
        }
        t -= NPAD;
        if (t < NZ1) { g_agg[t] = 0.0f; continue; }
        t -= NZ1;
        if (t < NZ2) { g_pool[t] = 0.0f; continue; }
        t -= NZ2;
        if (t < NZ3) { g_cnt[t] = 0; continue; }
        t -= NZ3;
        if (t < NR) {
            int i = t >> 6, h = t & 63;
            g_Bp[i * JB + 3392 + h] = root[t];   // root[i,h]
            continue;
        }
        t -= NR;
        g_Bp[IND * JB + t] = 0.0f;               // zero padded K-rows
    }
}

// ---------------- build C = W2 @ W1 and c0 into Bp -------------------------
// warp per output row m in [0, 15040); lane handles d = lane, lane+32
__global__ void buildC_kernel(const float* __restrict__ W1,
                              const float* __restrict__ b1,
                              const float* __restrict__ W2,
                              const float* __restrict__ b2) {
    int m = (blockIdx.x * blockDim.x + threadIdx.x) >> 5;
    int lane = threadIdx.x & 31;
    if (m >= MROWS) return;
    const float* w2row = W2 + m * 128;
    int d0 = lane, d1 = lane + 32;
    float acc0 = 0.f, acc1 = 0.f, accb = 0.f;
#pragma unroll 4
    for (int k = 0; k < 128; ++k) {
        float w2 = __ldg(w2row + k);             // broadcast across warp
        float w1a = __ldg(W1 + k * EDIM + d0);
        float w1b = (d1 < EDIM) ? __ldg(W1 + k * EDIM + d1) : 0.0f;
        acc0 = fmaf(w2, w1a, acc0);
        acc1 = fmaf(w2, w1b, acc1);
        accb = fmaf(w2, __ldg(b1 + k), accb);
    }
    int i = m >> 6, h = m & 63;
    float* brow = g_Bp + i * JB;
    brow[d0 * 64 + h] = acc0;
    if (d1 < EDIM) brow[d1 * 64 + h] = acc1;
    if (lane == 0) brow[3328 + h] = accb + b2[m];
}

// ---------------- main GEMM via tf32 tensor cores --------------------------
// U[8192,3456] = Xp[8192,240] @ Bp[240,3456]
// 128x128 tile, BK=16, 256 threads (8 warps, 2x4 grid of 64x32 warp tiles)
#define BM 128
#define BN 128
#define BKT 16
#define SAS 136   // shared stride (floats): (8k+m)%32 hits all banks -> conflict-free frags
__global__ void __launch_bounds__(256)
gemm_tf32_kernel() {
    __shared__ float As[BKT][SAS];   // [k][m]
    __shared__ float Bs[BKT][SAS];   // [k][n]

    const int tid  = threadIdx.x;
    const int lane = tid & 31;
    const int warp = tid >> 5;
    const int m0 = blockIdx.y * BM;
    const int n0 = blockIdx.x * BN;
    const int wm = (warp >> 2) * 64;   // warp tile 64x32
    const int wn = (warp & 3) * 32;

    // A global load map: row = tid>>1, k-span = (tid&1)*8 .. +8  (2 float4)
    const int ra = tid >> 1;
    const int ka = (tid & 1) * 8;
    const float* aptr = g_Xp + (m0 + ra) * KP + ka;
    // B global load map: k-row = tid>>4, n-span = (tid&15)*8 .. +8 (2 float4)
    const int kb = tid >> 4;
    const int nb = (tid & 15) * 8;
    const float* bptr = g_Bp + kb * JB + n0 + nb;

    float acc[4][4][4];
#pragma unroll
    for (int mt = 0; mt < 4; ++mt)
#pragma unroll
        for (int nt = 0; nt < 4; ++nt)
#pragma unroll
            for (int i = 0; i < 4; ++i) acc[mt][nt][i] = 0.0f;

    // prologue prefetch
    float4 pa0 = *(const float4*)(aptr);
    float4 pa1 = *(const float4*)(aptr + 4);
    float4 pb0 = *(const float4*)(bptr);
    float4 pb1 = *(const float4*)(bptr + 4);

    const int gid = lane >> 2;   // group id (0..7)
    const int tig = lane & 3;    // thread in group (0..3)

    for (int k0 = 0; k0 < KP; k0 += BKT) {
        // store (converted to tf32) into shared
        As[ka + 0][ra] = to_tf32(pa0.x);
        As[ka + 1][ra] = to_tf32(pa0.y);
        As[ka + 2][ra] = to_tf32(pa0.z);
        As[ka + 3][ra] = to_tf32(pa0.w);
        As[ka + 4][ra] = to_tf32(pa1.x);
        As[ka + 5][ra] = to_tf32(pa1.y);
        As[ka + 6][ra] = to_tf32(pa1.z);
        As[ka + 7][ra] = to_tf32(pa1.w);
        {
            float4 c0 = make_float4(to_tf32(pb0.x), to_tf32(pb0.y), to_tf32(pb0.z), to_tf32(pb0.w));
            float4 c1 = make_float4(to_tf32(pb1.x), to_tf32(pb1.y), to_tf32(pb1.z), to_tf32(pb1.w));
            *(float4*)&Bs[kb][nb]     = c0;
            *(float4*)&Bs[kb][nb + 4] = c1;
        }
        __syncthreads();

        if (k0 + BKT < KP) {
            pa0 = *(const float4*)(aptr + k0 + BKT);
            pa1 = *(const float4*)(aptr + k0 + BKT + 4);
            pb0 = *(const float4*)(bptr + (k0 + BKT) * JB);
            pb1 = *(const float4*)(bptr + (k0 + BKT) * JB + 4);
        }

#pragma unroll
        for (int ks = 0; ks < 2; ++ks) {
            const int kk = ks * 8 + tig;
            unsigned af[4][4];
#pragma unroll
            for (int mt = 0; mt < 4; ++mt) {
                int m = wm + mt * 16 + gid;
                af[mt][0] = __float_as_uint(As[kk][m]);
                af[mt][1] = __float_as_uint(As[kk][m + 8]);
                af[mt][2] = __float_as_uint(As[kk + 4][m]);
                af[mt][3] = __float_as_uint(As[kk + 4][m + 8]);
            }
#pragma unroll
            for (int nt = 0; nt < 4; ++nt) {
                int n = wn + nt * 8 + gid;
                unsigned b0 = __float_as_uint(Bs[kk][n]);
                unsigned b1 = __float_as_uint(Bs[kk + 4][n]);
#pragma unroll
                for (int mt = 0; mt < 4; ++mt)
                    mma_tf32(acc[mt][nt], af[mt][0], af[mt][1], af[mt][2], af[mt][3], b0, b1);
            }
        }
        __syncthreads();
    }

    // epilogue: c0,c1 -> (row, 2t), (row, 2t+1); c2,c3 -> row+8
#pragma unroll
    for (int mt = 0; mt < 4; ++mt) {
        int m = m0 + wm + mt * 16 + gid;
#pragma unroll
        for (int nt = 0; nt < 4; ++nt) {
            int n = n0 + wn + nt * 8 + 2 * tig;
            float* p = g_U + m * JB + n;
            *(float2*)p             = make_float2(acc[mt][nt][0], acc[mt][nt][1]);
            *(float2*)(p + 8 * JB)  = make_float2(acc[mt][nt][2], acc[mt][nt][3]);
        }
    }
}

// ---------------- edge kernel: gather U[src], contract ea, scatter to agg --
// warp per edge; lane handles h = 2*lane, 2*lane+1
__global__ void edge_kernel(const int* __restrict__ ei,
                            const float* __restrict__ ea) {
    int e = (blockIdx.x * blockDim.x + threadIdx.x) >> 5;
    int lane = threadIdx.x & 31;
    if (e >= EE) return;
    int src = ei[e];
    int dst = ei[EE + e];
    const float* urow = g_U + src * JB;
    const float* earow = ea + e * EDIM;

    float2 acc = *(const float2*)(urow + 3328 + 2 * lane);  // c0 contribution
#pragma unroll 4
    for (int d = 0; d < EDIM; ++d) {
        float ed = __ldg(earow + d);
        float2 u = *(const float2*)(urow + d * 64 + 2 * lane);
        acc.x = fmaf(ed, u.x, acc.x);
        acc.y = fmaf(ed, u.y, acc.y);
    }
    atomicAdd(&g_agg[dst * 64 + 2 * lane],     acc.x);
    atomicAdd(&g_agg[dst * 64 + 2 * lane + 1], acc.y);
}

// ---------------- node kernel: relu(agg + x@root + b), pool scatter --------
__global__ void node_kernel(const int* __restrict__ batch,
                            const float* __restrict__ conv_b) {
    int n = (blockIdx.x * blockDim.x + threadIdx.x) >> 5;
    int lane = threadIdx.x & 31;
    if (n >= NN) return;
    float2 a  = *(const float2*)&g_agg[n * 64 + 2 * lane];
    float2 xr = *(const float2*)(g_U + n * JB + 3392 + 2 * lane);
    float ox = fmaxf(a.x + xr.x + __ldg(conv_b + 2 * lane),     0.0f);
    float oy = fmaxf(a.y + xr.y + __ldg(conv_b + 2 * lane + 1), 0.0f);
    int g = batch[n];
    atomicAdd(&g_pool[g * 64 + 2 * lane],     ox);
    atomicAdd(&g_pool[g * 64 + 2 * lane + 1], oy);
    if (lane == 0) atomicAdd(&g_cnt[g], 1);
}

// ---------------- fused MLP head: block per graph --------------------------
__global__ void mlp_kernel(const float* __restrict__ fw1, const float* __restrict__ fb1,
                           const float* __restrict__ fw2, const float* __restrict__ fb2,
                           const float* __restrict__ fw3, const float* __restrict__ fb3,
                           const float* __restrict__ fw4, const float* __restrict__ fb4,
                           float* __restrict__ out) {
    int g = blockIdx.x;
    int t = threadIdx.x;
    __shared__ float s0[64], s1[128], s2[256], s3[128];

    if (t < 64) {
        float c = fmaxf((float)g_cnt[g], 1.0f);
        s0[t] = g_pool[g * 64 + t] / c;
    }
    __syncthreads();

    if (t < 128) {
        float a = fb1[t];
#pragma unroll 8
        for (int j = 0; j < 64; ++j) a = fmaf(__ldg(fw1 + t * 64 + j), s0[j], a);
        s1[t] = fmaxf(a, 0.0f);
    }
    __syncthreads();

    {
        float a = fb2[t];
#pragma unroll 8
        for (int j = 0; j < 128; ++j) a = fmaf(__ldg(fw2 + t * 128 + j), s1[j], a);
        s2[t] = fmaxf(a, 0.0f);
    }
    __syncthreads();

    if (t < 128) {
        float a = fb3[t];
#pragma unroll 8
        for (int j = 0; j < 256; ++j) a = fmaf(__ldg(fw3 + t * 256 + j), s2[j], a);
        s3[t] = fmaxf(a, 0.0f);
    }
    __syncthreads();

    if (t < 32) {
        float a = 0.0f;
        for (int j = t; j < 128; j += 32) a = fmaf(__ldg(fw4 + j), s3[j], a);
#pragma unroll
        for (int o = 16; o; o >>= 1) a += __shfl_down_sync(0xffffffffu, a, o);
        if (t == 0) out[g] = a + fb4[0];
    }
}

// ---------------- launcher -------------------------------------------------
extern "C" void kernel_launch(void* const* d_in, const int* in_sizes, int n_in,
                              void* d_out, int out_size) {
    const float* x      = (const float*)d_in[0];
    const int*   ei     = (const int*)  d_in[1];
    const float* ea     = (const float*)d_in[2];
    const int*   batch  = (const int*)  d_in[3];
    const float* W1     = (const float*)d_in[4];
    const float* b1     = (const float*)d_in[5];
    const float* W2     = (const float*)d_in[6];
    const float* b2     = (const float*)d_in[7];
    const float* root   = (const float*)d_in[8];
    const float* conv_b = (const float*)d_in[9];
    const float* fw1    = (const float*)d_in[10];
    const float* fb1    = (const float*)d_in[11];
    const float* fw2    = (const float*)d_in[12];
    const float* fb2    = (const float*)d_in[13];
    const float* fw3    = (const float*)d_in[14];
    const float* fb3    = (const float*)d_in[15];
    const float* fw4    = (const float*)d_in[16];
    const float* fb4    = (const float*)d_in[17];
    float* out = (float*)d_out;

    prep_kernel<<<4096, 256>>>(x, root);
    buildC_kernel<<<(MROWS + 7) / 8, 256>>>(W1, b1, W2, b2);
    gemm_tf32_kernel<<<dim3(JB / BN, NN / BM), 256>>>();
    edge_kernel<<<EE / 8, 256>>>(ei, ea);
    node_kernel<<<NN / 8, 256>>>(batch, conv_b);
    mlp_kernel<<<GG, 256>>>(fw1, fb1, fw2, fb2, fw3, fb3, fw4, fb4, out);
}